// round 5
// baseline (speedup 1.0000x reference)
#include <cuda_runtime.h>
#include <math.h>

#define NN 50000
#define EE 800000

// ---------------- scratch (static __device__, no runtime allocation) ----------------
__device__ float g_dis[NN];          // (deg+1)^-1/2
__device__ int   g_deg[NN];          // in-degree (edges only)
__device__ int   g_off[NN + 1];      // CSR offsets (by destination col)
__device__ int   g_cur[NN];          // scatter cursors
__device__ int   g_rows[EE];         // raw row per edge
__device__ int   g_cols[EE];         // raw col per edge
__device__ int   g_srows[EE];        // CSR-sorted source row
__device__ float g_senorm[EE];       // CSR-sorted edge weight dis[row]*dis[col]
__device__ float g_Afc[NN * 192];    // Agg([feature | condition])
__device__ float g_H2 [NN * 256];    // [f2h | c2h]
__device__ float g_HD [NN * 256];    // [z2h | c2h_d]
__device__ float g_P  [NN * 64];     // h @ [W_mean | W_logvar]   (pre-agg)
__device__ float g_Az [NN * 32];     // Agg(z)
__device__ float g_O  [NN * 128];    // hd @ W_out (pre-agg)
__device__ float g_Wml[256 * 64];    // [W_mean | W_logvar] packed
__device__ float g_bml[64];          // [b_mean | b_logvar] packed

// ---------------- CSR build ----------------
// Per-block dtype vote: view data as int64; values out of [0,n) for any lane
// mean the underlying dtype is int32 (pairs of indices pack into one int64).
__global__ void k_convert(const void* p, int e, int n) {
    int i = blockIdx.x * 256 + threadIdx.x;
    const long long* q64 = (const long long*)p;
    long long probe = 0;
    if (i < e) probe = q64[i];
    int okl = (probe >= 0 && probe < (long long)n) ? 1 : 0;
    int is64 = __syncthreads_and(okl);
    if (i >= e) return;
    int r, c;
    if (is64) {
        r = (int)probe;
        c = (int)q64[e + i];
    } else {
        const int* q32 = (const int*)p;
        r = q32[i];
        c = q32[e + i];
    }
    g_rows[i] = r;
    g_cols[i] = c;
    atomicAdd(&g_deg[c], 1);
}

// single-block scan of degrees -> offsets + cursors + dis
__global__ void k_scan(int n, int e) {
    __shared__ int part[1024];
    int t = threadIdx.x;
    int chunk = (n + 1023) / 1024;
    int s = t * chunk;
    int en = s + chunk; if (en > n) en = n;
    int sum = 0;
    for (int i = s; i < en; i++) sum += g_deg[i];
    part[t] = sum;
    __syncthreads();
    for (int off = 1; off < 1024; off <<= 1) {
        int v = (t >= off) ? part[t - off] : 0;
        __syncthreads();
        part[t] += v;
        __syncthreads();
    }
    int base = (t == 0) ? 0 : part[t - 1];
    for (int i = s; i < en; i++) {
        g_off[i] = base;
        g_cur[i] = base;
        base += g_deg[i];
        g_dis[i] = rsqrtf((float)g_deg[i] + 1.0f);
    }
    if (t == 1023) g_off[n] = e;
}

// scatter edges into CSR order; extra blocks pack Wml/bml
__global__ void k_scatter(int e,
                          const float* __restrict__ Wm, const float* __restrict__ Wl,
                          const float* __restrict__ bm, const float* __restrict__ bl) {
    int i = blockIdx.x * 256 + threadIdx.x;
    if (i < e) {
        int r = g_rows[i], c = g_cols[i];
        int pos = atomicAdd(&g_cur[c], 1);
        g_srows[pos]  = r;
        g_senorm[pos] = g_dis[r] * g_dis[c];
    } else {
        int j = i - e;
        if (j < 256 * 64) {
            int k = j / 64, col = j % 64;
            g_Wml[j] = (col < 32) ? Wm[k * 32 + col] : Wl[k * 32 + (col - 32)];
        }
        if (j < 64) g_bml[j] = (j < 32) ? bm[j] : bl[j - 32];
    }
}

// ---------------- CSR aggregation: dst[i] = d_i^2*src[i] + sum_e w_e*src[row_e] (+bias) ----------------
template<int C0, int C1, bool BIAS>
__global__ __launch_bounds__(256) void k_aggc(
    const float4* __restrict__ s0, const float4* __restrict__ s1,
    const float4* __restrict__ bias, float4* __restrict__ dst, int n)
{
    constexpr int CT = C0 + C1;
    int idx = blockIdx.x * 256 + threadIdx.x;
    if (idx >= n * CT) return;
    int i = idx / CT, c = idx % CT;

    const float4* __restrict__ base;
    int stride;
    if (C1 == 0 || c < C0) { base = s0 + c;        stride = C0; }
    else                   { base = s1 + (c - C0); stride = C1; }

    float d = g_dis[i];
    float w0 = d * d;
    float4 v = base[(size_t)i * stride];
    float4 acc;
    acc.x = v.x * w0; acc.y = v.y * w0; acc.z = v.z * w0; acc.w = v.w * w0;

    int b = g_off[i], bend = g_off[i + 1];
    #pragma unroll 4
    for (int eix = b; eix < bend; eix++) {
        int   r = g_srows[eix];
        float w = g_senorm[eix];
        float4 u = base[(size_t)r * stride];
        acc.x += u.x * w; acc.y += u.y * w; acc.z += u.z * w; acc.w += u.w * w;
    }
    if (BIAS) {
        float4 bb = bias[c];
        acc.x += bb.x; acc.y += bb.y; acc.z += bb.z; acc.w += bb.w;
    }
    dst[(size_t)i * CT + c] = acc;
}

// ---------------- fused pass B: Agg(P)+bias, then reparameterize ----------------
// P is [mean(32) | logvar(32)] per node = 16 float4; thread handles chunk c of
// mean (c) and logvar (c+8), then z = noise*exp(0.5*lv)+m.
__global__ __launch_bounds__(256) void k_aggB(
    const float4* __restrict__ P, const float4* __restrict__ noise,
    float4* __restrict__ oz, float4* __restrict__ om, float4* __restrict__ olv, int n)
{
    int idx = blockIdx.x * 256 + threadIdx.x;
    if (idx >= n * 8) return;
    int i = idx / 8, c = idx % 8;

    float d = g_dis[i];
    float w0 = d * d;
    float4 vm = P[(size_t)i * 16 + c];
    float4 vl = P[(size_t)i * 16 + c + 8];
    float4 am, al;
    am.x = vm.x * w0; am.y = vm.y * w0; am.z = vm.z * w0; am.w = vm.w * w0;
    al.x = vl.x * w0; al.y = vl.y * w0; al.z = vl.z * w0; al.w = vl.w * w0;

    int b = g_off[i], bend = g_off[i + 1];
    #pragma unroll 4
    for (int eix = b; eix < bend; eix++) {
        int   r = g_srows[eix];
        float w = g_senorm[eix];
        float4 um = P[(size_t)r * 16 + c];
        float4 ul = P[(size_t)r * 16 + c + 8];
        am.x += um.x * w; am.y += um.y * w; am.z += um.z * w; am.w += um.w * w;
        al.x += ul.x * w; al.y += ul.y * w; al.z += ul.z * w; al.w += ul.w * w;
    }
    const float4* bml4 = (const float4*)g_bml;
    float4 bm = bml4[c], blv = bml4[c + 8];
    am.x += bm.x;  am.y += bm.y;  am.z += bm.z;  am.w += bm.w;
    al.x += blv.x; al.y += blv.y; al.z += blv.z; al.w += blv.w;

    float4 nv = noise[idx];
    float4 zv;
    zv.x = nv.x * expf(0.5f * al.x) + am.x;
    zv.y = nv.y * expf(0.5f * al.y) + am.y;
    zv.z = nv.z * expf(0.5f * al.z) + am.z;
    zv.w = nv.w * expf(0.5f * al.w) + am.w;

    oz[idx]  = zv;
    om[idx]  = am;
    olv[idx] = al;
}

// ---------------- tiled GEMM: C[M,NC] = A[M,K] @ W[K,NC] (+bias) (tanh) ----------------
template<int K, int NC, bool BIAS, bool TANH>
__global__ __launch_bounds__(256, 2) void k_gemm8(
    const float* __restrict__ A, int lda,
    const float* __restrict__ W, const float* __restrict__ bias,
    float* __restrict__ C, int ldc, int M)
{
    constexpr int COLT = NC / 8;
    constexpr int ROWT = 256 / COLT;
    constexpr int TM   = ROWT * 8;
    constexpr int LDA_S = TM + 4;
    __shared__ float sA[16][LDA_S];
    __shared__ float sW[16][NC];

    int tid = threadIdx.x;
    int m0  = blockIdx.x * TM;
    int tx  = tid % COLT, ty = tid / COLT;
    int c0  = tx * 8, r0 = ty * 8;

    float acc[8][8];
    #pragma unroll
    for (int i = 0; i < 8; i++)
        #pragma unroll
        for (int j = 0; j < 8; j++) acc[i][j] = 0.0f;

    for (int k0 = 0; k0 < K; k0 += 16) {
        #pragma unroll
        for (int f = tid; f < TM * 4; f += 256) {
            int r = f >> 2, kk4 = (f & 3) * 4;
            float4 av = make_float4(0.f, 0.f, 0.f, 0.f);
            int gr = m0 + r;
            if (gr < M) av = *(const float4*)&A[(size_t)gr * lda + k0 + kk4];
            sA[kk4 + 0][r] = av.x;
            sA[kk4 + 1][r] = av.y;
            sA[kk4 + 2][r] = av.z;
            sA[kk4 + 3][r] = av.w;
        }
        #pragma unroll
        for (int f = tid; f < 4 * NC; f += 256) {
            int kk = f / (NC / 4), c4 = f % (NC / 4);
            *(float4*)&sW[kk][c4 * 4] = *(const float4*)&W[(size_t)(k0 + kk) * NC + c4 * 4];
        }
        __syncthreads();
        #pragma unroll
        for (int kk = 0; kk < 16; kk++) {
            float4 a0 = *(const float4*)&sA[kk][r0];
            float4 a1 = *(const float4*)&sA[kk][r0 + 4];
            float4 w0 = *(const float4*)&sW[kk][c0];
            float4 w1 = *(const float4*)&sW[kk][c0 + 4];
            float av[8] = {a0.x, a0.y, a0.z, a0.w, a1.x, a1.y, a1.z, a1.w};
            float wv[8] = {w0.x, w0.y, w0.z, w0.w, w1.x, w1.y, w1.z, w1.w};
            #pragma unroll
            for (int i = 0; i < 8; i++)
                #pragma unroll
                for (int j = 0; j < 8; j++)
                    acc[i][j] += av[i] * wv[j];
        }
        __syncthreads();
    }

    float4 bv0 = make_float4(0.f, 0.f, 0.f, 0.f);
    float4 bv1 = make_float4(0.f, 0.f, 0.f, 0.f);
    if (BIAS) {
        bv0 = *(const float4*)&bias[c0];
        bv1 = *(const float4*)&bias[c0 + 4];
    }
    #pragma unroll
    for (int i = 0; i < 8; i++) {
        int gr = m0 + r0 + i;
        if (gr >= M) continue;
        float4 o0, o1;
        o0.x = acc[i][0] + bv0.x; o0.y = acc[i][1] + bv0.y;
        o0.z = acc[i][2] + bv0.z; o0.w = acc[i][3] + bv0.w;
        o1.x = acc[i][4] + bv1.x; o1.y = acc[i][5] + bv1.y;
        o1.z = acc[i][6] + bv1.z; o1.w = acc[i][7] + bv1.w;
        if (TANH) {
            o0.x = tanhf(o0.x); o0.y = tanhf(o0.y); o0.z = tanhf(o0.z); o0.w = tanhf(o0.w);
            o1.x = tanhf(o1.x); o1.y = tanhf(o1.y); o1.z = tanhf(o1.z); o1.w = tanhf(o1.w);
        }
        *(float4*)&C[(size_t)gr * ldc + c0]     = o0;
        *(float4*)&C[(size_t)gr * ldc + c0 + 4] = o1;
    }
}

// ---------------- launch ----------------
static inline int cdiv(int a, int b) { return (a + b - 1) / b; }

extern "C" void kernel_launch(void* const* d_in, const int* in_sizes, int n_in,
                              void* d_out, int out_size) {
    const float* feature   = (const float*)d_in[0];
    const float* condition = (const float*)d_in[1];
    const float* noise     = (const float*)d_in[2];
    const float* W_f2h     = (const float*)d_in[3];
    const float* b_f2h     = (const float*)d_in[4];
    const float* W_c2h_e   = (const float*)d_in[5];
    const float* b_c2h_e   = (const float*)d_in[6];
    const float* W_mean    = (const float*)d_in[7];
    const float* b_mean    = (const float*)d_in[8];
    const float* W_logvar  = (const float*)d_in[9];
    const float* b_logvar  = (const float*)d_in[10];
    const float* W_z2h     = (const float*)d_in[11];
    const float* b_z2h     = (const float*)d_in[12];
    const float* W_c2h_d   = (const float*)d_in[13];
    const float* b_c2h_d   = (const float*)d_in[14];
    const float* W_out     = (const float*)d_in[15];
    const float* b_out     = (const float*)d_in[16];
    const void*  eidx      = d_in[17];

    int n = in_sizes[0] / 128;
    int e = in_sizes[17] / 2;

    float* oz  = (float*)d_out;
    float* om  = oz  + (size_t)n * 32;
    float* olv = om  + (size_t)n * 32;
    float* oo  = olv + (size_t)n * 32;

    void *pAfc, *pH2, *pHD, *pP, *pAz, *pO, *pWml, *pDeg;
    cudaGetSymbolAddress(&pAfc, g_Afc);
    cudaGetSymbolAddress(&pH2,  g_H2);
    cudaGetSymbolAddress(&pHD,  g_HD);
    cudaGetSymbolAddress(&pP,   g_P);
    cudaGetSymbolAddress(&pAz,  g_Az);
    cudaGetSymbolAddress(&pO,   g_O);
    cudaGetSymbolAddress(&pWml, g_Wml);
    cudaGetSymbolAddress(&pDeg, g_deg);
    float* Afc = (float*)pAfc;
    float* H2  = (float*)pH2;
    float* HD  = (float*)pHD;
    float* P   = (float*)pP;
    float* Az  = (float*)pAz;
    float* O   = (float*)pO;
    float* Wml = (float*)pWml;

    // ---- CSR build (deg zeroed via memset node, not a kernel launch) ----
    cudaMemsetAsync(pDeg, 0, (size_t)n * sizeof(int));
    k_convert<<<cdiv(e, 256), 256>>>(eidx, e, n);                            // launch 0
    k_scan<<<1, 1024>>>(n, e);                                               // launch 1
    k_scatter<<<cdiv(e + 256 * 64, 256), 256>>>(e, W_mean, W_logvar,
                                                b_mean, b_logvar);           // launch 2

    // Pass A: Afc = Agg([feature|condition])  width 192                     // launch 3 (profiled)
    k_aggc<32, 16, false><<<cdiv(n * 48, 256), 256>>>(
        (const float4*)feature, (const float4*)condition, nullptr, (float4*)Afc, n);

    // Encoder projections (bias + tanh)
    k_gemm8<128, 128, true, true><<<cdiv(n, 128), 256>>>(Afc,       192, W_f2h,   b_f2h,   H2,       256, n);
    k_gemm8< 64, 128, true, true><<<cdiv(n, 128), 256>>>(Afc + 128, 192, W_c2h_e, b_c2h_e, H2 + 128, 256, n);
    k_gemm8< 64, 128, true, true><<<cdiv(n, 128), 256>>>(Afc + 128, 192, W_c2h_d, b_c2h_d, HD + 128, 256, n);

    // mean+logvar fused projection
    k_gemm8<256, 64, false, false><<<cdiv(n, 256), 256>>>(H2, 256, Wml, nullptr, P, 64, n);

    // Pass B fused with reparameterization
    k_aggB<<<cdiv(n * 8, 256), 256>>>((const float4*)P, (const float4*)noise,
                                      (float4*)oz, (float4*)om, (float4*)olv, n);

    // Pass C: Az = Agg(z)  width 32
    k_aggc<8, 0, false><<<cdiv(n * 8, 256), 256>>>(
        (const float4*)oz, nullptr, nullptr, (float4*)Az, n);

    // Decoder
    k_gemm8< 32, 128, true,  true ><<<cdiv(n, 128), 256>>>(Az, 32,  W_z2h, b_z2h, HD, 256, n);
    k_gemm8<256, 128, false, false><<<cdiv(n, 128), 256>>>(HD, 256, W_out, nullptr, O, 128, n);

    // Pass D: out = Agg(O) + b_out  width 128
    k_aggc<32, 0, true><<<cdiv(n * 32, 256), 256>>>(
        (const float4*)O, nullptr, (const float4*)b_out, (float4*)oo, n);
}

// round 6
// speedup vs baseline: 1.3303x; 1.3303x over previous
#include <cuda_runtime.h>
#include <cuda_bf16.h>
#include <math.h>
#include <stdint.h>

#define NN 50000
#define EE 800000

// ---------------- scratch (static __device__, no runtime allocation) ----------------
__device__ float g_dis[NN];          // (deg+1)^-1/2
__device__ int   g_deg[NN];          // in-degree (edges only)
__device__ int   g_off[NN + 1];      // CSR offsets (by destination col)
__device__ int   g_cur[NN];          // scatter cursors
__device__ int   g_rows[EE];         // raw row per edge
__device__ int   g_cols[EE];         // raw col per edge
__device__ int   g_srows[EE];        // CSR-sorted source row
__device__ float g_senorm[EE];       // CSR-sorted edge weight dis[row]*dis[col]
__device__ float g_Afc[NN * 192];    // Agg([feature | condition])
__device__ float g_H2 [NN * 256];    // [f2h | c2h]
__device__ float g_HD [NN * 256];    // [z2h | c2h_d]
__device__ float g_P  [NN * 64];     // h @ [W_mean | W_logvar]   (pre-agg)
__device__ float g_Az [NN * 32];     // Agg(z)
__device__ float g_O  [NN * 128];    // hd @ W_out (pre-agg)
__device__ float g_Wml[256 * 64];    // [W_mean | W_logvar] packed
__device__ float g_bml[64];          // [b_mean | b_logvar] packed

// ---------------- CSR build ----------------
__global__ void k_convert(const void* p, int e, int n) {
    int i = blockIdx.x * 256 + threadIdx.x;
    const long long* q64 = (const long long*)p;
    long long probe = 0;
    if (i < e) probe = q64[i];
    int okl = (probe >= 0 && probe < (long long)n) ? 1 : 0;
    int is64 = __syncthreads_and(okl);
    if (i >= e) return;
    int r, c;
    if (is64) {
        r = (int)probe;
        c = (int)q64[e + i];
    } else {
        const int* q32 = (const int*)p;
        r = q32[i];
        c = q32[e + i];
    }
    g_rows[i] = r;
    g_cols[i] = c;
    atomicAdd(&g_deg[c], 1);
}

__global__ void k_scan(int n, int e) {
    __shared__ int part[1024];
    int t = threadIdx.x;
    int chunk = (n + 1023) / 1024;
    int s = t * chunk;
    int en = s + chunk; if (en > n) en = n;
    int sum = 0;
    for (int i = s; i < en; i++) sum += g_deg[i];
    part[t] = sum;
    __syncthreads();
    for (int off = 1; off < 1024; off <<= 1) {
        int v = (t >= off) ? part[t - off] : 0;
        __syncthreads();
        part[t] += v;
        __syncthreads();
    }
    int base = (t == 0) ? 0 : part[t - 1];
    for (int i = s; i < en; i++) {
        g_off[i] = base;
        g_cur[i] = base;
        base += g_deg[i];
        g_dis[i] = rsqrtf((float)g_deg[i] + 1.0f);
    }
    if (t == 1023) g_off[n] = e;
}

__global__ void k_scatter(int e,
                          const float* __restrict__ Wm, const float* __restrict__ Wl,
                          const float* __restrict__ bm, const float* __restrict__ bl) {
    int i = blockIdx.x * 256 + threadIdx.x;
    if (i < e) {
        int r = g_rows[i], c = g_cols[i];
        int pos = atomicAdd(&g_cur[c], 1);
        g_srows[pos]  = r;
        g_senorm[pos] = g_dis[r] * g_dis[c];
    } else {
        int j = i - e;
        if (j < 256 * 64) {
            int k = j / 64, col = j % 64;
            g_Wml[j] = (col < 32) ? Wm[k * 32 + col] : Wl[k * 32 + (col - 32)];
        }
        if (j < 64) g_bml[j] = (j < 32) ? bm[j] : bl[j - 32];
    }
}

// ---------------- CSR aggregation ----------------
template<int C0, int C1, bool BIAS>
__global__ __launch_bounds__(256) void k_aggc(
    const float4* __restrict__ s0, const float4* __restrict__ s1,
    const float4* __restrict__ bias, float4* __restrict__ dst, int n)
{
    constexpr int CT = C0 + C1;
    int idx = blockIdx.x * 256 + threadIdx.x;
    if (idx >= n * CT) return;
    int i = idx / CT, c = idx % CT;

    const float4* __restrict__ base;
    int stride;
    if (C1 == 0 || c < C0) { base = s0 + c;        stride = C0; }
    else                   { base = s1 + (c - C0); stride = C1; }

    float d = g_dis[i];
    float w0 = d * d;
    float4 v = base[(size_t)i * stride];
    float4 acc;
    acc.x = v.x * w0; acc.y = v.y * w0; acc.z = v.z * w0; acc.w = v.w * w0;

    int b = g_off[i], bend = g_off[i + 1];
    #pragma unroll 4
    for (int eix = b; eix < bend; eix++) {
        int   r = g_srows[eix];
        float w = g_senorm[eix];
        float4 u = base[(size_t)r * stride];
        acc.x += u.x * w; acc.y += u.y * w; acc.z += u.z * w; acc.w += u.w * w;
    }
    if (BIAS) {
        float4 bb = bias[c];
        acc.x += bb.x; acc.y += bb.y; acc.z += bb.z; acc.w += bb.w;
    }
    dst[(size_t)i * CT + c] = acc;
}

// ---------------- fused pass B: Agg(P)+bias, then reparameterize ----------------
__global__ __launch_bounds__(256) void k_aggB(
    const float4* __restrict__ P, const float4* __restrict__ noise,
    float4* __restrict__ oz, float4* __restrict__ om, float4* __restrict__ olv, int n)
{
    int idx = blockIdx.x * 256 + threadIdx.x;
    if (idx >= n * 8) return;
    int i = idx / 8, c = idx % 8;

    float d = g_dis[i];
    float w0 = d * d;
    float4 vm = P[(size_t)i * 16 + c];
    float4 vl = P[(size_t)i * 16 + c + 8];
    float4 am, al;
    am.x = vm.x * w0; am.y = vm.y * w0; am.z = vm.z * w0; am.w = vm.w * w0;
    al.x = vl.x * w0; al.y = vl.y * w0; al.z = vl.z * w0; al.w = vl.w * w0;

    int b = g_off[i], bend = g_off[i + 1];
    #pragma unroll 4
    for (int eix = b; eix < bend; eix++) {
        int   r = g_srows[eix];
        float w = g_senorm[eix];
        float4 um = P[(size_t)r * 16 + c];
        float4 ul = P[(size_t)r * 16 + c + 8];
        am.x += um.x * w; am.y += um.y * w; am.z += um.z * w; am.w += um.w * w;
        al.x += ul.x * w; al.y += ul.y * w; al.z += ul.z * w; al.w += ul.w * w;
    }
    const float4* bml4 = (const float4*)g_bml;
    float4 bm = bml4[c], blv = bml4[c + 8];
    am.x += bm.x;  am.y += bm.y;  am.z += bm.z;  am.w += bm.w;
    al.x += blv.x; al.y += blv.y; al.z += blv.z; al.w += blv.w;

    float4 nv = noise[idx];
    float4 zv;
    zv.x = nv.x * expf(0.5f * al.x) + am.x;
    zv.y = nv.y * expf(0.5f * al.y) + am.y;
    zv.z = nv.z * expf(0.5f * al.z) + am.z;
    zv.w = nv.w * expf(0.5f * al.w) + am.w;

    oz[idx]  = zv;
    om[idx]  = am;
    olv[idx] = al;
}

// ---------------- bf16 split-precision tensor-core GEMM ----------------
// C[M,NC] = A[M,K] @ W[K,NC] (+bias)(tanh), fp32 in/out.
// x = hi + lo (bf16 each); C = Ahi*Whi + Ahi*Wlo + Alo*Whi  (error ~1.5e-5 rel).
// Block: 256 thr (8 warps, 2x4), tile 128 x NC, BK=32.
__device__ __forceinline__ void mma_bf16(float* d,
    uint32_t a0, uint32_t a1, uint32_t a2, uint32_t a3,
    uint32_t b0, uint32_t b1)
{
    asm volatile(
        "mma.sync.aligned.m16n8k16.row.col.f32.bf16.bf16.f32 "
        "{%0,%1,%2,%3}, {%4,%5,%6,%7}, {%8,%9}, {%0,%1,%2,%3};\n"
        : "+f"(d[0]), "+f"(d[1]), "+f"(d[2]), "+f"(d[3])
        : "r"(a0), "r"(a1), "r"(a2), "r"(a3), "r"(b0), "r"(b1));
}

template<int K, int NC, bool BIAS, bool TANH>
__global__ __launch_bounds__(256) void k_gemm_bf16(
    const float* __restrict__ A, int lda,
    const float* __restrict__ W, const float* __restrict__ bias,
    float* __restrict__ C, int ldc, int M)
{
    constexpr int BM = 128;
    constexpr int BK = 32;
    constexpr int PA = 20;        // bf162 row stride for sA (conflict-free)
    constexpr int PW = NC + 8;    // bf162 row stride for sW (conflict-free)
    constexpr int WN = NC / 4;    // cols per warp
    constexpr int NJ = WN / 8;    // n8 tiles per warp (4 or 2)

    __shared__ __nv_bfloat162 sAhi[BM * PA];
    __shared__ __nv_bfloat162 sAlo[BM * PA];
    __shared__ __nv_bfloat16  sWhi[16 * PW * 2];
    __shared__ __nv_bfloat16  sWlo[16 * PW * 2];

    int tid  = threadIdx.x;
    int lane = tid & 31;
    int wid  = tid >> 5;
    int warpM = wid >> 2, warpN = wid & 3;
    int wr0 = warpM * 64;
    int wc0 = warpN * WN;
    int g = lane >> 2, q = lane & 3;
    int m0 = blockIdx.x * BM;

    float acc[4][NJ][4];
    #pragma unroll
    for (int mi = 0; mi < 4; mi++)
        #pragma unroll
        for (int nj = 0; nj < NJ; nj++)
            #pragma unroll
            for (int t = 0; t < 4; t++) acc[mi][nj][t] = 0.0f;

    const uint32_t* ah32 = (const uint32_t*)sAhi;
    const uint32_t* al32 = (const uint32_t*)sAlo;
    const uint32_t* wh32 = (const uint32_t*)sWhi;
    const uint32_t* wl32 = (const uint32_t*)sWlo;

    for (int k0 = 0; k0 < K; k0 += BK) {
        // ---- A tile: 128x32 floats -> hi/lo bf162 pairs ----
        #pragma unroll
        for (int f = tid; f < BM * BK / 4; f += 256) {
            int r = f >> 3, k4 = (f & 7) * 4;
            float4 v = make_float4(0.f, 0.f, 0.f, 0.f);
            int gr = m0 + r;
            if (gr < M) v = *(const float4*)&A[(size_t)gr * lda + k0 + k4];
            int p0 = k4 >> 1;
            __nv_bfloat16 hx = __float2bfloat16_rn(v.x);
            __nv_bfloat16 hy = __float2bfloat16_rn(v.y);
            __nv_bfloat16 hz = __float2bfloat16_rn(v.z);
            __nv_bfloat16 hw = __float2bfloat16_rn(v.w);
            __nv_bfloat162 h01; h01.x = hx; h01.y = hy;
            __nv_bfloat162 h23; h23.x = hz; h23.y = hw;
            __nv_bfloat162 l01, l23;
            l01.x = __float2bfloat16_rn(v.x - __bfloat162float(hx));
            l01.y = __float2bfloat16_rn(v.y - __bfloat162float(hy));
            l23.x = __float2bfloat16_rn(v.z - __bfloat162float(hz));
            l23.y = __float2bfloat16_rn(v.w - __bfloat162float(hw));
            sAhi[r * PA + p0]     = h01;
            sAhi[r * PA + p0 + 1] = h23;
            sAlo[r * PA + p0]     = l01;
            sAlo[r * PA + p0 + 1] = l23;
        }
        // ---- W tile: 32xNC floats -> hi/lo, k-pairs vertical ----
        #pragma unroll
        for (int f = tid; f < 8 * NC; f += 256) {
            int kk = f / (NC / 4);
            int n4 = (f % (NC / 4)) * 4;
            float4 w = *(const float4*)&W[(size_t)(k0 + kk) * NC + n4];
            int kp = kk >> 1, h = kk & 1;
            int base = (kp * PW + n4) * 2 + h;
            float wv[4] = {w.x, w.y, w.z, w.w};
            #pragma unroll
            for (int j = 0; j < 4; j++) {
                __nv_bfloat16 hb = __float2bfloat16_rn(wv[j]);
                sWhi[base + 2 * j] = hb;
                sWlo[base + 2 * j] = __float2bfloat16_rn(wv[j] - __bfloat162float(hb));
            }
        }
        __syncthreads();

        #pragma unroll
        for (int s = 0; s < 2; s++) {
            uint32_t bh[NJ][2], bl[NJ][2];
            int kp0 = s * 8 + q;
            #pragma unroll
            for (int nj = 0; nj < NJ; nj++) {
                int n = wc0 + nj * 8 + g;
                bh[nj][0] = wh32[kp0 * PW + n];
                bh[nj][1] = wh32[(kp0 + 4) * PW + n];
                bl[nj][0] = wl32[kp0 * PW + n];
                bl[nj][1] = wl32[(kp0 + 4) * PW + n];
            }
            #pragma unroll
            for (int mi = 0; mi < 4; mi++) {
                int r = wr0 + mi * 16 + g;
                uint32_t ah0 = ah32[r * PA + kp0];
                uint32_t ah1 = ah32[(r + 8) * PA + kp0];
                uint32_t ah2 = ah32[r * PA + kp0 + 4];
                uint32_t ah3 = ah32[(r + 8) * PA + kp0 + 4];
                uint32_t al0 = al32[r * PA + kp0];
                uint32_t al1 = al32[(r + 8) * PA + kp0];
                uint32_t al2 = al32[r * PA + kp0 + 4];
                uint32_t al3 = al32[(r + 8) * PA + kp0 + 4];
                #pragma unroll
                for (int nj = 0; nj < NJ; nj++) {
                    mma_bf16(acc[mi][nj], ah0, ah1, ah2, ah3, bh[nj][0], bh[nj][1]);
                    mma_bf16(acc[mi][nj], ah0, ah1, ah2, ah3, bl[nj][0], bl[nj][1]);
                    mma_bf16(acc[mi][nj], al0, al1, al2, al3, bh[nj][0], bh[nj][1]);
                }
            }
        }
        __syncthreads();
    }

    // ---- epilogue ----
    #pragma unroll
    for (int mi = 0; mi < 4; mi++) {
        #pragma unroll
        for (int nj = 0; nj < NJ; nj++) {
            int c  = wc0 + nj * 8 + 2 * q;
            float b0v = 0.f, b1v = 0.f;
            if (BIAS) { b0v = bias[c]; b1v = bias[c + 1]; }
            int r0 = m0 + wr0 + mi * 16 + g;
            float v0 = acc[mi][nj][0] + b0v;
            float v1 = acc[mi][nj][1] + b1v;
            float v2 = acc[mi][nj][2] + b0v;
            float v3 = acc[mi][nj][3] + b1v;
            if (TANH) { v0 = tanhf(v0); v1 = tanhf(v1); v2 = tanhf(v2); v3 = tanhf(v3); }
            if (r0 < M) {
                float2 o; o.x = v0; o.y = v1;
                *(float2*)&C[(size_t)r0 * ldc + c] = o;
            }
            if (r0 + 8 < M) {
                float2 o; o.x = v2; o.y = v3;
                *(float2*)&C[(size_t)(r0 + 8) * ldc + c] = o;
            }
        }
    }
}

// ---------------- launch ----------------
static inline int cdiv(int a, int b) { return (a + b - 1) / b; }

extern "C" void kernel_launch(void* const* d_in, const int* in_sizes, int n_in,
                              void* d_out, int out_size) {
    const float* feature   = (const float*)d_in[0];
    const float* condition = (const float*)d_in[1];
    const float* noise     = (const float*)d_in[2];
    const float* W_f2h     = (const float*)d_in[3];
    const float* b_f2h     = (const float*)d_in[4];
    const float* W_c2h_e   = (const float*)d_in[5];
    const float* b_c2h_e   = (const float*)d_in[6];
    const float* W_mean    = (const float*)d_in[7];
    const float* b_mean    = (const float*)d_in[8];
    const float* W_logvar  = (const float*)d_in[9];
    const float* b_logvar  = (const float*)d_in[10];
    const float* W_z2h     = (const float*)d_in[11];
    const float* b_z2h     = (const float*)d_in[12];
    const float* W_c2h_d   = (const float*)d_in[13];
    const float* b_c2h_d   = (const float*)d_in[14];
    const float* W_out     = (const float*)d_in[15];
    const float* b_out     = (const float*)d_in[16];
    const void*  eidx      = d_in[17];

    int n = in_sizes[0] / 128;
    int e = in_sizes[17] / 2;

    float* oz  = (float*)d_out;
    float* om  = oz  + (size_t)n * 32;
    float* olv = om  + (size_t)n * 32;
    float* oo  = olv + (size_t)n * 32;

    void *pAfc, *pH2, *pHD, *pP, *pAz, *pO, *pWml, *pDeg;
    cudaGetSymbolAddress(&pAfc, g_Afc);
    cudaGetSymbolAddress(&pH2,  g_H2);
    cudaGetSymbolAddress(&pHD,  g_HD);
    cudaGetSymbolAddress(&pP,   g_P);
    cudaGetSymbolAddress(&pAz,  g_Az);
    cudaGetSymbolAddress(&pO,   g_O);
    cudaGetSymbolAddress(&pWml, g_Wml);
    cudaGetSymbolAddress(&pDeg, g_deg);
    float* Afc = (float*)pAfc;
    float* H2  = (float*)pH2;
    float* HD  = (float*)pHD;
    float* P   = (float*)pP;
    float* Az  = (float*)pAz;
    float* O   = (float*)pO;
    float* Wml = (float*)pWml;

    // ---- CSR build ----
    cudaMemsetAsync(pDeg, 0, (size_t)n * sizeof(int));
    k_convert<<<cdiv(e, 256), 256>>>(eidx, e, n);
    k_scan<<<1, 1024>>>(n, e);
    k_scatter<<<cdiv(e + 256 * 64, 256), 256>>>(e, W_mean, W_logvar, b_mean, b_logvar);

    // Pass A: Afc = Agg([feature|condition])  width 192   (profiled launch)
    k_aggc<32, 16, false><<<cdiv(n * 48, 256), 256>>>(
        (const float4*)feature, (const float4*)condition, nullptr, (float4*)Afc, n);

    // Encoder projections (bias + tanh)
    k_gemm_bf16<128, 128, true, true><<<cdiv(n, 128), 256>>>(Afc,       192, W_f2h,   b_f2h,   H2,       256, n);
    k_gemm_bf16< 64, 128, true, true><<<cdiv(n, 128), 256>>>(Afc + 128, 192, W_c2h_e, b_c2h_e, H2 + 128, 256, n);
    k_gemm_bf16< 64, 128, true, true><<<cdiv(n, 128), 256>>>(Afc + 128, 192, W_c2h_d, b_c2h_d, HD + 128, 256, n);

    // mean+logvar fused projection
    k_gemm_bf16<256, 64, false, false><<<cdiv(n, 128), 256>>>(H2, 256, Wml, nullptr, P, 64, n);

    // Pass B fused with reparameterization
    k_aggB<<<cdiv(n * 8, 256), 256>>>((const float4*)P, (const float4*)noise,
                                      (float4*)oz, (float4*)om, (float4*)olv, n);

    // Pass C: Az = Agg(z)  width 32
    k_aggc<8, 0, false><<<cdiv(n * 8, 256), 256>>>(
        (const float4*)oz, nullptr, nullptr, (float4*)Az, n);

    // Decoder
    k_gemm_bf16< 32, 128, true,  true ><<<cdiv(n, 128), 256>>>(Az, 32,  W_z2h, b_z2h, HD, 256, n);
    k_gemm_bf16<256, 128, false, false><<<cdiv(n, 128), 256>>>(HD, 256, W_out, nullptr, O, 128, n);

    // Pass D: out = Agg(O) + b_out  width 128
    k_aggc<32, 0, true><<<cdiv(n * 32, 256), 256>>>(
        (const float4*)O, nullptr, (const float4*)b_out, (float4*)oo, n);
}